// round 1
// baseline (speedup 1.0000x reference)
#include <cuda_runtime.h>

// R2Ntab: out[b] = (# rules r with h[b,r] > 0.999999) * [w_or>0] + b_or
// where h[b,r] = x_b . rw_r + b_and[r] - relu(rw_r).sum(),
//       rw_r = w_and_r with columns zeroed where w_cancel < 0.
//
// Since x is binary {0,1}: x.rw <= relu_sum with deficit = sum |w| over
// "mismatched" features. Pass <=> deficit < eps_r, eps_r = b_and[r]-0.999999.
// For |w| >= eps_r on every care feature this is EXACTLY a 256-bit pattern
// match: (x_bits & care_r) == pos_r. Tiny weights (|w| < eps) become
// don't-care if their total < eps; otherwise the rule falls back to an exact
// fp32 dot (flagged, expected count 0 for this data).

#define FDIM 256
#define RDIM 128

// Bit layout: feature f = h*128 + 4*j + c  ->  word w = h*4 + c, bit j.
// (Matches the float4-load + ballot packing in the main kernel.)

__device__ unsigned g_pos[8][RDIM];
__device__ unsigned g_care[8][RDIM];
__device__ float    g_thresh[RDIM];      // relu_sum - eps   (exact-path threshold on dot)
__device__ float    g_rw[RDIM * FDIM];   // masked weights   (exact-path operand)
__device__ int      g_exact_flag[RDIM];

// ---------------------------------------------------------------------------
// Prep: one warp per rule. Builds pos/care masks, exact-path data, flags.
// ---------------------------------------------------------------------------
__global__ void prep_kernel(const float* __restrict__ wc,
                            const float* __restrict__ wa,
                            const float* __restrict__ ba,
                            const float* __restrict__ wo) {
    int gt   = blockIdx.x * blockDim.x + threadIdx.x;
    int r    = gt >> 5;
    int lane = gt & 31;
    if (r >= RDIM) return;

    float eps     = ba[r] - 0.999999f;
    bool  include = wo[r] > 0.0f;      // w_or[0][r] > 0 gates the rule into the sum

    float relu_sum = 0.f, sum_tiny = 0.f;
    unsigned pos[8], care[8];
#pragma unroll
    for (int h = 0; h < 2; h++) {
#pragma unroll
        for (int c = 0; c < 4; c++) {
            int   w  = h * 4 + c;
            int   f  = h * 128 + 4 * lane + c;
            float wv = (wc[f] < 0.f) ? 0.f : wa[r * FDIM + f];
            g_rw[r * FDIM + f] = wv;
            relu_sum += fmaxf(wv, 0.f);
            float aw   = fabsf(wv);
            bool  must = (aw >= eps);           // big enough that a mismatch alone fails
            if (!must) sum_tiny += aw;          // tiny -> don't-care candidate
            pos[w]  = __ballot_sync(0xffffffffu, must && (wv > 0.f));
            care[w] = __ballot_sync(0xffffffffu, must && (wv != 0.f));
        }
    }
#pragma unroll
    for (int o = 16; o; o >>= 1) {
        relu_sum += __shfl_xor_sync(0xffffffffu, relu_sum, o);
        sum_tiny += __shfl_xor_sync(0xffffffffu, sum_tiny, o);
    }

    bool afalse = (!include) || (eps <= 0.f);        // rule can never fire / is gated out
    bool exact  = (!afalse) && (sum_tiny >= eps);    // don't-care set too heavy: exact path
    if (afalse || exact) {
        // Impossible mask: (x & 0) == 0xFFFFFFFF is never true -> fast-path reject.
#pragma unroll
        for (int w = 0; w < 8; w++) { pos[w] = 0u; care[w] = 0u; }
        pos[0] = 0xFFFFFFFFu;
    }
    if (lane == 0) {
        g_thresh[r]     = relu_sum - eps;
        g_exact_flag[r] = exact ? 1 : 0;
#pragma unroll
        for (int w = 0; w < 8; w++) { g_pos[w][r] = pos[w]; g_care[w][r] = care[w]; }
    }
}

// ---------------------------------------------------------------------------
// Main: one warp per row. 2x LDG.128 (coalesced), 8 ballots, word-0 mask test
// per rule with rare full-check / exact-dot fallbacks. HBM-bound by design.
// ---------------------------------------------------------------------------
__global__ void __launch_bounds__(256)
main_kernel(const float* __restrict__ x,
            const float* __restrict__ bor,
            float* __restrict__ out, int B) {
    __shared__ unsigned s_pos[8][RDIM];
    __shared__ unsigned s_care[8][RDIM];
    __shared__ int s_nx;
    __shared__ int s_xr[RDIM];

    int tid = threadIdx.x;
    if (tid == 0) s_nx = 0;
    __syncthreads();
    for (int i = tid; i < 8 * RDIM; i += blockDim.x) {
        (&s_pos[0][0])[i]  = (&g_pos[0][0])[i];
        (&s_care[0][0])[i] = (&g_care[0][0])[i];
    }
    if (tid < RDIM) {
        if (g_exact_flag[tid]) {
            int i = atomicAdd(&s_nx, 1);
            s_xr[i] = tid;
        }
    }
    __syncthreads();

    int   lane = tid & 31;
    int   nx   = s_nx;
    float b0   = bor[0];

    // Word-0 masks for this lane's 4 rules (lane, lane+32, lane+64, lane+96),
    // hoisted to registers: the fast path never touches shared memory.
    unsigned p0[4], c0[4];
#pragma unroll
    for (int k = 0; k < 4; k++) {
        p0[k] = s_pos[0][lane + 32 * k];
        c0[k] = s_care[0][lane + 32 * k];
    }

    int gw = blockIdx.x * (blockDim.x >> 5) + (tid >> 5);
    int nw = gridDim.x * (blockDim.x >> 5);

    for (int row = gw; row < B; row += nw) {
        const float4* xr = (const float4*)(x + (size_t)row * FDIM);
        float4 a = xr[lane];        // features [4*lane .. 4*lane+3]
        float4 b = xr[lane + 32];   // features [128+4*lane .. 128+4*lane+3]

        unsigned xw0 = __ballot_sync(0xffffffffu, a.x > 0.5f);
        unsigned xw1 = __ballot_sync(0xffffffffu, a.y > 0.5f);
        unsigned xw2 = __ballot_sync(0xffffffffu, a.z > 0.5f);
        unsigned xw3 = __ballot_sync(0xffffffffu, a.w > 0.5f);
        unsigned xw4 = __ballot_sync(0xffffffffu, b.x > 0.5f);
        unsigned xw5 = __ballot_sync(0xffffffffu, b.y > 0.5f);
        unsigned xw6 = __ballot_sync(0xffffffffu, b.z > 0.5f);
        unsigned xw7 = __ballot_sync(0xffffffffu, b.w > 0.5f);

        // Fast reject: does ANY rule in the warp survive the word-0 test?
        bool cand = false;
#pragma unroll
        for (int k = 0; k < 4; k++)
            cand |= (((xw0 & c0[k]) ^ p0[k]) == 0u);
        unsigned any = __ballot_sync(0xffffffffu, cand);

        if (any == 0u && nx == 0) {            // warp-uniform branch (the ~always case)
            if (lane == 0) out[row] = b0;      // zero matching rules
            continue;
        }

        unsigned xw[8] = {xw0, xw1, xw2, xw3, xw4, xw5, xw6, xw7};
        int cnt = 0;
#pragma unroll
        for (int k = 0; k < 4; k++) {
            int r = lane + 32 * k;
            unsigned acc = (xw0 & c0[k]) ^ p0[k];
            if (acc == 0u) {
#pragma unroll
                for (int w = 1; w < 8; w++)
                    acc |= (xw[w] & s_care[w][r]) ^ s_pos[w][r];
                if (acc == 0u) cnt++;
            }
        }
        // Exact fp32 fallback for flagged rules (expected: nx == 0).
        for (int e = 0; e < nx; e++) {
            int r = s_xr[e];
            float s = 0.f;
#pragma unroll
            for (int h = 0; h < 2; h++)
#pragma unroll
                for (int c = 0; c < 4; c++) {
                    int w = h * 4 + c;
                    int f = h * 128 + 4 * lane + c;
                    if ((xw[w] >> lane) & 1u)
                        s += g_rw[r * FDIM + f];
                }
#pragma unroll
            for (int o = 16; o; o >>= 1)
                s += __shfl_xor_sync(0xffffffffu, s, o);
            if (lane == 0 && s > g_thresh[r]) cnt++;
        }
#pragma unroll
        for (int o = 16; o; o >>= 1)
            cnt += __shfl_xor_sync(0xffffffffu, cnt, o);
        if (lane == 0) out[row] = (float)cnt + b0;
    }
}

extern "C" void kernel_launch(void* const* d_in, const int* in_sizes, int n_in,
                              void* d_out, int out_size) {
    const float* x  = (const float*)d_in[0];   // [B, 256] binary
    const float* wc = (const float*)d_in[1];   // [256]
    const float* wa = (const float*)d_in[2];   // [128, 256]
    const float* ba = (const float*)d_in[3];   // [128]
    const float* wo = (const float*)d_in[4];   // [1, 128]
    const float* bo = (const float*)d_in[5];   // [1]
    float* out = (float*)d_out;

    int B = in_sizes[0] / FDIM;

    prep_kernel<<<4, 1024>>>(wc, wa, ba, wo);          // 128 warps, 1 per rule
    main_kernel<<<1184, 256>>>(x, bo, out, B);         // 8 blocks/SM, grid-stride
}

// round 3
// speedup vs baseline: 1.1826x; 1.1826x over previous
#include <cuda_runtime.h>

// R2Ntab: out[b] = (# rules r with h[b,r] > 0.999999) * [w_or>0] + b_or
// where h[b,r] = x_b . rw_r + b_and[r] - relu(rw_r).sum(),
//       rw_r = w_and_r with columns zeroed where w_cancel < 0.
//
// x is binary {0,1}: x.rw <= relu_sum with deficit = sum |w| over mismatched
// features. Pass <=> deficit < eps_r (= b_and[r]-0.999999). When every care
// weight has |w| >= eps this is EXACTLY a 256-bit pattern match:
// (x_bits & care_r) == pos_r. Tiny weights become don't-care if their total
// < eps; otherwise that rule is flagged for an exact fp32 dot fallback.

#define FDIM 256
#define RDIM 128
#define UNROLL 4

// Bit layout: feature f = h*128 + 4*j + c  ->  word w = h*4 + c, bit j.

__device__ unsigned g_pos[8][RDIM];
__device__ unsigned g_care[8][RDIM];
__device__ float    g_thresh[RDIM];
__device__ float    g_rw[RDIM * FDIM];
__device__ int      g_exact_flag[RDIM];

// ---------------------------------------------------------------------------
// Prep: one warp per rule.
// ---------------------------------------------------------------------------
__global__ void prep_kernel(const float* __restrict__ wc,
                            const float* __restrict__ wa,
                            const float* __restrict__ ba,
                            const float* __restrict__ wo) {
    int gt   = blockIdx.x * blockDim.x + threadIdx.x;
    int r    = gt >> 5;
    int lane = gt & 31;
    if (r >= RDIM) return;

    float eps     = ba[r] - 0.999999f;
    bool  include = wo[r] > 0.0f;

    float relu_sum = 0.f, sum_tiny = 0.f;
    unsigned pos[8], care[8];
#pragma unroll
    for (int h = 0; h < 2; h++) {
#pragma unroll
        for (int c = 0; c < 4; c++) {
            int   w  = h * 4 + c;
            int   f  = h * 128 + 4 * lane + c;
            float wv = (wc[f] < 0.f) ? 0.f : wa[r * FDIM + f];
            g_rw[r * FDIM + f] = wv;
            relu_sum += fmaxf(wv, 0.f);
            float aw   = fabsf(wv);
            bool  must = (aw >= eps);
            if (!must) sum_tiny += aw;
            pos[w]  = __ballot_sync(0xffffffffu, must && (wv > 0.f));
            care[w] = __ballot_sync(0xffffffffu, must && (wv != 0.f));
        }
    }
#pragma unroll
    for (int o = 16; o; o >>= 1) {
        relu_sum += __shfl_xor_sync(0xffffffffu, relu_sum, o);
        sum_tiny += __shfl_xor_sync(0xffffffffu, sum_tiny, o);
    }

    bool afalse = (!include) || (eps <= 0.f);
    bool exact  = (!afalse) && (sum_tiny >= eps);
    if (afalse || exact) {
#pragma unroll
        for (int w = 0; w < 8; w++) { pos[w] = 0u; care[w] = 0u; }
        pos[0] = 0xFFFFFFFFu;   // (x & 0) == 0xFFFFFFFF: never matches
    }
    if (lane == 0) {
        g_thresh[r]     = relu_sum - eps;
        g_exact_flag[r] = exact ? 1 : 0;
#pragma unroll
        for (int w = 0; w < 8; w++) { g_pos[w][r] = pos[w]; g_care[w][r] = care[w]; }
    }
}

// ---------------------------------------------------------------------------
// Main: warp per row, 4 rows per iteration for MLP=8. Fast path per row:
// 2 ballots + 4 LOP3/ISETP. Streaming loads (read-once data).
// ---------------------------------------------------------------------------
__global__ void __launch_bounds__(256, 4)
main_kernel(const float* __restrict__ x,
            const float* __restrict__ bor,
            float* __restrict__ out, int B) {
    __shared__ unsigned s_pos[8][RDIM];
    __shared__ unsigned s_care[8][RDIM];
    __shared__ int s_nx;
    __shared__ int s_xr[RDIM];

    int tid = threadIdx.x;
    if (tid == 0) s_nx = 0;
    __syncthreads();
    for (int i = tid; i < 8 * RDIM; i += blockDim.x) {
        (&s_pos[0][0])[i]  = (&g_pos[0][0])[i];
        (&s_care[0][0])[i] = (&g_care[0][0])[i];
    }
    if (tid < RDIM && g_exact_flag[tid]) {
        int i = atomicAdd(&s_nx, 1);
        s_xr[i] = tid;
    }
    __syncthreads();

    const int   lane = tid & 31;
    const int   nx   = s_nx;
    const float b0   = bor[0];

    // Word-0 masks for this lane's 4 rules, register-resident.
    unsigned p0[4], c0[4];
#pragma unroll
    for (int k = 0; k < 4; k++) {
        p0[k] = s_pos[0][lane + 32 * k];
        c0[k] = s_care[0][lane + 32 * k];
    }

    const int gw = blockIdx.x * (blockDim.x >> 5) + (tid >> 5);
    const int nw = gridDim.x * (blockDim.x >> 5);
    const int nchunks = B / UNROLL;          // B = 131072 -> 32768

    for (int ch = gw; ch < nchunks; ch += nw) {
        int row0 = ch * UNROLL;

        // Issue all 8 loads up front (independent -> MLP=8).
        float4 a[UNROLL], b[UNROLL];
#pragma unroll
        for (int u = 0; u < UNROLL; u++) {
            const float4* xr = (const float4*)(x + (size_t)(row0 + u) * FDIM);
            a[u] = __ldcs(&xr[lane]);
            b[u] = __ldcs(&xr[lane + 32]);
        }

        // Per-thread byte: bit w = this lane's bit of x-word w for row u.
        unsigned bits[UNROLL];
#pragma unroll
        for (int u = 0; u < UNROLL; u++) {
            bits[u] =  (a[u].x > 0.5f)
                    | ((a[u].y > 0.5f) << 1)
                    | ((a[u].z > 0.5f) << 2)
                    | ((a[u].w > 0.5f) << 3)
                    | ((b[u].x > 0.5f) << 4)
                    | ((b[u].y > 0.5f) << 5)
                    | ((b[u].z > 0.5f) << 6)
                    | ((b[u].w > 0.5f) << 7);
        }

#pragma unroll
        for (int u = 0; u < UNROLL; u++) {
            unsigned xw0 = __ballot_sync(0xffffffffu, bits[u] & 1u);
            bool cand = false;
#pragma unroll
            for (int k = 0; k < 4; k++)
                cand |= (((xw0 & c0[k]) ^ p0[k]) == 0u);
            unsigned any = __ballot_sync(0xffffffffu, cand);

            if (any == 0u && nx == 0) {              // warp-uniform, ~always
                if (lane == 0) out[row0 + u] = b0;
                continue;
            }

            // Rare path: build the remaining 7 words, run full checks.
            unsigned xw[8];
            xw[0] = xw0;
#pragma unroll
            for (int w = 1; w < 8; w++)
                xw[w] = __ballot_sync(0xffffffffu, (bits[u] >> w) & 1u);

            int cnt = 0;
#pragma unroll
            for (int k = 0; k < 4; k++) {
                int r = lane + 32 * k;
                unsigned acc = (xw0 & c0[k]) ^ p0[k];
                if (acc == 0u) {
#pragma unroll
                    for (int w = 1; w < 8; w++)
                        acc |= (xw[w] & s_care[w][r]) ^ s_pos[w][r];
                    if (acc == 0u) cnt++;
                }
            }
            // Exact fp32 fallback for flagged rules (expected nx == 0).
            for (int e = 0; e < nx; e++) {
                int r = s_xr[e];
                float s = 0.f;
#pragma unroll
                for (int w = 0; w < 8; w++) {
                    if ((xw[w] >> lane) & 1u) {
                        int h = w >> 2, c = w & 3;
                        s += g_rw[r * FDIM + h * 128 + 4 * lane + c];
                    }
                }
#pragma unroll
                for (int o = 16; o; o >>= 1)
                    s += __shfl_xor_sync(0xffffffffu, s, o);
                if (lane == 0 && s > g_thresh[r]) cnt++;
            }
#pragma unroll
            for (int o = 16; o; o >>= 1)
                cnt += __shfl_xor_sync(0xffffffffu, cnt, o);
            if (lane == 0) out[row0 + u] = (float)cnt + b0;
        }
    }

    // Tail rows (B not divisible by UNROLL): single-row path.
    for (int row = nchunks * UNROLL + gw; row < B; row += nw) {
        const float4* xr = (const float4*)(x + (size_t)row * FDIM);
        float4 a = __ldcs(&xr[lane]);
        float4 b = __ldcs(&xr[lane + 32]);
        unsigned bits =  (a.x > 0.5f) | ((a.y > 0.5f) << 1)
                      | ((a.z > 0.5f) << 2) | ((a.w > 0.5f) << 3)
                      | ((b.x > 0.5f) << 4) | ((b.y > 0.5f) << 5)
                      | ((b.z > 0.5f) << 6) | ((b.w > 0.5f) << 7);
        unsigned xw[8];
#pragma unroll
        for (int w = 0; w < 8; w++)
            xw[w] = __ballot_sync(0xffffffffu, (bits >> w) & 1u);
        int cnt = 0;
#pragma unroll
        for (int k = 0; k < 4; k++) {
            int r = lane + 32 * k;
            unsigned acc = 0u;
#pragma unroll
            for (int w = 0; w < 8; w++)
                acc |= (xw[w] & s_care[w][r]) ^ s_pos[w][r];
            if (acc == 0u) cnt++;
        }
        for (int e = 0; e < nx; e++) {
            int r = s_xr[e];
            float s = 0.f;
#pragma unroll
            for (int w = 0; w < 8; w++) {
                if ((xw[w] >> lane) & 1u) {
                    int h = w >> 2, c = w & 3;
                    s += g_rw[r * FDIM + h * 128 + 4 * lane + c];
                }
            }
#pragma unroll
            for (int o = 16; o; o >>= 1)
                s += __shfl_xor_sync(0xffffffffu, s, o);
            if (lane == 0 && s > g_thresh[r]) cnt++;
        }
#pragma unroll
        for (int o = 16; o; o >>= 1)
            cnt += __shfl_xor_sync(0xffffffffu, cnt, o);
        if (lane == 0) out[row] = (float)cnt + b0;
    }
}

extern "C" void kernel_launch(void* const* d_in, const int* in_sizes, int n_in,
                              void* d_out, int out_size) {
    const float* x  = (const float*)d_in[0];   // [B, 256] binary
    const float* wc = (const float*)d_in[1];   // [256]
    const float* wa = (const float*)d_in[2];   // [128, 256]
    const float* ba = (const float*)d_in[3];   // [128]
    const float* wo = (const float*)d_in[4];   // [1, 128]
    const float* bo = (const float*)d_in[5];   // [1]
    float* out = (float*)d_out;

    int B = in_sizes[0] / FDIM;

    prep_kernel<<<4, 1024>>>(wc, wa, ba, wo);      // 128 warps, 1 per rule
    main_kernel<<<592, 256>>>(x, bo, out, B);      // 4 blocks/SM, persistent wave
}